// round 3
// baseline (speedup 1.0000x reference)
#include <cuda_runtime.h>
#include <cstdint>

#define BB 8
#define SEQ 1024
#define DM 512
#define NH 8
#define DK 64

// Scratch (allocation-free rule: __device__ globals).
__device__ float g_q[BB * NH * SEQ * DK];
__device__ float g_k[BB * NH * SEQ * DK];
__device__ float g_v[BB * NH * SEQ * DK];
__device__ float g_hd[BB * SEQ * DM];
__device__ uint8_t g_mask8[(size_t)BB * SEQ * SEQ];
__device__ unsigned g_flags[2];   // [0]: some word not in {0,1}; [1]: some byte not in {0,1}

// ---------------------------------------------------------------------------
// Mask dtype detection. Sample 64K words (256KB, valid for uint8/int32/f32
// interpretations alike). int32 bool -> all words in {0,1}. uint8 bool ->
// words >1 exist but all bytes in {0,1}. float32 bool -> bytes outside {0,1}.
// ---------------------------------------------------------------------------
__global__ void mask_detect(const unsigned* __restrict__ m)
{
    __shared__ unsigned s0, s1;
    if (threadIdx.x == 0) { s0 = 0u; s1 = 0u; }
    __syncthreads();
    unsigned a0 = 0u, a1 = 0u;
    for (int i = threadIdx.x; i < 65536; i += blockDim.x) {
        const unsigned w = m[i];
        if (w > 1u) a0 = 1u;
        const unsigned b = w | (w >> 8) | (w >> 16) | (w >> 24);
        if (b & 0xFEu) a1 = 1u;
    }
    if (a0) atomicOr(&s0, 1u);
    if (a1) atomicOr(&s1, 1u);
    __syncthreads();
    if (threadIdx.x == 0) { g_flags[0] = s0; g_flags[1] = s1; }
}

// Canonicalize mask into g_mask8 (1 byte per element, nonzero = masked).
// kind: 0 = int32, 1 = uint8, 2 = float32. One thread = 4 elements.
__global__ __launch_bounds__(256) void mask_convert(const void* __restrict__ mraw)
{
    const size_t i = (size_t)blockIdx.x * 256 + threadIdx.x;  // 0 .. 2M-1
    const unsigned kind = (g_flags[0] == 0u) ? 0u : ((g_flags[1] == 0u) ? 1u : 2u);
    uchar4 o;
    if (kind == 0u) {
        const int4 v = reinterpret_cast<const int4*>(mraw)[i];
        o.x = (v.x != 0); o.y = (v.y != 0); o.z = (v.z != 0); o.w = (v.w != 0);
    } else if (kind == 1u) {
        o = reinterpret_cast<const uchar4*>(mraw)[i];
    } else {
        const float4 v = reinterpret_cast<const float4*>(mraw)[i];
        o.x = (v.x != 0.0f); o.y = (v.y != 0.0f);
        o.z = (v.z != 0.0f); o.w = (v.w != 0.0f);
    }
    reinterpret_cast<uchar4*>(g_mask8)[i] = o;
}

// ---------------------------------------------------------------------------
// Kernel 1: QKV projections. GEMM M=8192, N=512, K=512; z selects Wq/Wk/Wv.
// Tile 64x64x16, 256 threads, 4x4 per thread.
// ---------------------------------------------------------------------------
__global__ __launch_bounds__(256) void qkv_kernel(
    const float* __restrict__ x,
    const float* __restrict__ Wq,
    const float* __restrict__ Wk,
    const float* __restrict__ Wv)
{
    __shared__ float As[16][64];   // [k][m]
    __shared__ float Bs[16][64];   // [k][n]

    const int t = blockIdx.z;
    const float* __restrict__ W = (t == 0) ? Wq : ((t == 1) ? Wk : Wv);
    float* __restrict__ outp = (t == 0) ? g_q : ((t == 1) ? g_k : g_v);

    const int m0 = blockIdx.x * 64;
    const int n0 = blockIdx.y * 64;
    const int h  = n0 >> 6;

    const int tid = threadIdx.x;
    const int tx = tid & 15;
    const int ty = tid >> 4;

    const int lm  = tid & 63;
    const int lk4 = tid >> 6;
    const int bkk = tid >> 4;
    const int bc4 = tid & 15;

    float acc[4][4];
#pragma unroll
    for (int i = 0; i < 4; i++)
#pragma unroll
        for (int j = 0; j < 4; j++) acc[i][j] = 0.0f;

    for (int k0 = 0; k0 < DM; k0 += 16) {
        float4 av = *reinterpret_cast<const float4*>(
            &x[(size_t)(m0 + lm) * DM + k0 + lk4 * 4]);
        As[lk4 * 4 + 0][lm] = av.x;
        As[lk4 * 4 + 1][lm] = av.y;
        As[lk4 * 4 + 2][lm] = av.z;
        As[lk4 * 4 + 3][lm] = av.w;

        float4 bv = *reinterpret_cast<const float4*>(
            &W[(size_t)h * DM * DK + (size_t)(k0 + bkk) * DK + bc4 * 4]);
        *reinterpret_cast<float4*>(&Bs[bkk][bc4 * 4]) = bv;

        __syncthreads();

#pragma unroll
        for (int kk = 0; kk < 16; kk++) {
            float4 a4 = *reinterpret_cast<const float4*>(&As[kk][ty * 4]);
            float4 b4 = *reinterpret_cast<const float4*>(&Bs[kk][tx * 4]);
            float a[4] = {a4.x, a4.y, a4.z, a4.w};
            float b[4] = {b4.x, b4.y, b4.z, b4.w};
#pragma unroll
            for (int i = 0; i < 4; i++)
#pragma unroll
                for (int j = 0; j < 4; j++)
                    acc[i][j] = fmaf(a[i], b[j], acc[i][j]);
        }
        __syncthreads();
    }

#pragma unroll
    for (int i = 0; i < 4; i++) {
        const int m = m0 + ty * 4 + i;
        const int b = m >> 10;
        const int n = m & 1023;
        float4 o4 = make_float4(acc[i][0], acc[i][1], acc[i][2], acc[i][3]);
        *reinterpret_cast<float4*>(
            &outp[(((size_t)b * NH + h) * SEQ + n) * DK + tx * 4]) = o4;
    }
}

// ---------------------------------------------------------------------------
// Kernel 2: flash attention per (b, h, 64-row tile).
// ---------------------------------------------------------------------------
__global__ __launch_bounds__(256) void attn_kernel()
{
    __shared__ float Qs[64][64];
    __shared__ float Kst[64][64];   // K^T in phase 1, P in phase 2
    __shared__ float Vs[64][64];

    const int r0 = blockIdx.x * 64;
    const int h  = blockIdx.y;
    const int b  = blockIdx.z;

    const int tid = threadIdx.x;
    const int tx = tid & 15;
    const int ty = tid >> 4;

    const size_t bh = (size_t)b * NH + h;
    const float* __restrict__ Qg = &g_q[bh * SEQ * DK];
    const float* __restrict__ Kg = &g_k[bh * SEQ * DK];
    const float* __restrict__ Vg = &g_v[bh * SEQ * DK];
    const uint8_t* __restrict__ Mg = &g_mask8[(size_t)b * SEQ * SEQ];

#pragma unroll
    for (int it = 0; it < 4; it++) {
        const int idx = tid + it * 256;
        const int qm = idx >> 4;
        const int qd = (idx & 15) * 4;
        *reinterpret_cast<float4*>(&Qs[qm][qd]) =
            *reinterpret_cast<const float4*>(&Qg[(size_t)(r0 + qm) * DK + qd]);
    }

    float o[4][4];
    float mi[4], li[4];
#pragma unroll
    for (int i = 0; i < 4; i++) {
        mi[i] = -1e30f;      // scores >= -1e9, first tile always dominates
        li[i] = 0.0f;
#pragma unroll
        for (int j = 0; j < 4; j++) o[i][j] = 0.0f;
    }

    const int km  = tid & 63;
    const int ks4 = tid >> 6;

    for (int m0 = 0; m0 < SEQ; m0 += 64) {
#pragma unroll
        for (int it = 0; it < 4; it++) {
            const int d0 = (ks4 + it * 4) * 4;
            float4 kv = *reinterpret_cast<const float4*>(
                &Kg[(size_t)(m0 + km) * DK + d0]);
            Kst[d0 + 0][km] = kv.x;
            Kst[d0 + 1][km] = kv.y;
            Kst[d0 + 2][km] = kv.z;
            Kst[d0 + 3][km] = kv.w;
        }
#pragma unroll
        for (int it = 0; it < 4; it++) {
            const int idx = tid + it * 256;
            const int vm = idx >> 4;
            const int vd = (idx & 15) * 4;
            *reinterpret_cast<float4*>(&Vs[vm][vd]) =
                *reinterpret_cast<const float4*>(&Vg[(size_t)(m0 + vm) * DK + vd]);
        }
        __syncthreads();

        // Phase 1: S = Q K^T
        float s[4][4];
#pragma unroll
        for (int i = 0; i < 4; i++)
#pragma unroll
            for (int j = 0; j < 4; j++) s[i][j] = 0.0f;

#pragma unroll
        for (int d = 0; d < 64; d += 4) {
            float qv[4][4];
#pragma unroll
            for (int i = 0; i < 4; i++) {
                float4 q4 = *reinterpret_cast<const float4*>(&Qs[ty * 4 + i][d]);
                qv[i][0] = q4.x; qv[i][1] = q4.y; qv[i][2] = q4.z; qv[i][3] = q4.w;
            }
#pragma unroll
            for (int c = 0; c < 4; c++) {
                float4 k4 = *reinterpret_cast<const float4*>(&Kst[d + c][tx * 4]);
                float kv[4] = {k4.x, k4.y, k4.z, k4.w};
#pragma unroll
                for (int i = 0; i < 4; i++)
#pragma unroll
                    for (int j = 0; j < 4; j++)
                        s[i][j] = fmaf(qv[i][c], kv[j], s[i][j]);
            }
        }
        __syncthreads();

        // Softmax update + write P tile (aliases Kst)
#pragma unroll
        for (int i = 0; i < 4; i++) {
            const int gr = r0 + ty * 4 + i;
            uchar4 mk = *reinterpret_cast<const uchar4*>(
                &Mg[(size_t)gr * SEQ + m0 + tx * 4]);
            float sv[4];
            sv[0] = mk.x ? -1e9f : s[i][0] * 0.125f;
            sv[1] = mk.y ? -1e9f : s[i][1] * 0.125f;
            sv[2] = mk.z ? -1e9f : s[i][2] * 0.125f;
            sv[3] = mk.w ? -1e9f : s[i][3] * 0.125f;

            float rm = fmaxf(fmaxf(sv[0], sv[1]), fmaxf(sv[2], sv[3]));
#pragma unroll
            for (int w = 1; w < 16; w <<= 1)
                rm = fmaxf(rm, __shfl_xor_sync(0xffffffffu, rm, w));

            const float nm = fmaxf(mi[i], rm);
            const float corr = __expf(mi[i] - nm);
            float p[4];
            float rs = 0.0f;
#pragma unroll
            for (int j = 0; j < 4; j++) {
                p[j] = __expf(sv[j] - nm);
                rs += p[j];
            }
#pragma unroll
            for (int w = 1; w < 16; w <<= 1)
                rs += __shfl_xor_sync(0xffffffffu, rs, w);

            li[i] = li[i] * corr + rs;
            mi[i] = nm;
#pragma unroll
            for (int j = 0; j < 4; j++) o[i][j] *= corr;

            Kst[ty * 4 + i][tx * 4 + 0] = p[0];
            Kst[ty * 4 + i][tx * 4 + 1] = p[1];
            Kst[ty * 4 + i][tx * 4 + 2] = p[2];
            Kst[ty * 4 + i][tx * 4 + 3] = p[3];
        }
        __syncthreads();

        // Phase 2: O += P V
#pragma unroll
        for (int m = 0; m < 64; m++) {
            float4 v4 = *reinterpret_cast<const float4*>(&Vs[m][tx * 4]);
            float vv[4] = {v4.x, v4.y, v4.z, v4.w};
            float pv[4];
#pragma unroll
            for (int i = 0; i < 4; i++) pv[i] = Kst[ty * 4 + i][m];
#pragma unroll
            for (int i = 0; i < 4; i++)
#pragma unroll
                for (int j = 0; j < 4; j++)
                    o[i][j] = fmaf(pv[i], vv[j], o[i][j]);
        }
        __syncthreads();
    }

    // Normalize + write heads as [B, N, H*64]
#pragma unroll
    for (int i = 0; i < 4; i++) {
        const float inv = 1.0f / li[i];
        const int n = r0 + ty * 4 + i;
        float4 o4 = make_float4(o[i][0] * inv, o[i][1] * inv,
                                o[i][2] * inv, o[i][3] * inv);
        *reinterpret_cast<float4*>(
            &g_hd[((size_t)b * SEQ + n) * DM + h * DK + tx * 4]) = o4;
    }
}

// ---------------------------------------------------------------------------
// Kernel 3: output projection (head-sum folded into K=512 reduction).
// ---------------------------------------------------------------------------
__global__ __launch_bounds__(256) void proj_kernel(
    const float* __restrict__ Wo, float* __restrict__ outp)
{
    __shared__ float As[16][64];
    __shared__ float Bs[16][64];

    const int m0 = blockIdx.x * 64;
    const int n0 = blockIdx.y * 64;

    const int tid = threadIdx.x;
    const int tx = tid & 15;
    const int ty = tid >> 4;

    const int lm  = tid & 63;
    const int lk4 = tid >> 6;
    const int bkk = tid >> 4;
    const int bc4 = tid & 15;

    float acc[4][4];
#pragma unroll
    for (int i = 0; i < 4; i++)
#pragma unroll
        for (int j = 0; j < 4; j++) acc[i][j] = 0.0f;

    for (int k0 = 0; k0 < DM; k0 += 16) {
        float4 av = *reinterpret_cast<const float4*>(
            &g_hd[(size_t)(m0 + lm) * DM + k0 + lk4 * 4]);
        As[lk4 * 4 + 0][lm] = av.x;
        As[lk4 * 4 + 1][lm] = av.y;
        As[lk4 * 4 + 2][lm] = av.z;
        As[lk4 * 4 + 3][lm] = av.w;

        float4 bv = *reinterpret_cast<const float4*>(
            &Wo[(size_t)(k0 + bkk) * DM + n0 + bc4 * 4]);
        *reinterpret_cast<float4*>(&Bs[bkk][bc4 * 4]) = bv;

        __syncthreads();

#pragma unroll
        for (int kk = 0; kk < 16; kk++) {
            float4 a4 = *reinterpret_cast<const float4*>(&As[kk][ty * 4]);
            float4 b4 = *reinterpret_cast<const float4*>(&Bs[kk][tx * 4]);
            float a[4] = {a4.x, a4.y, a4.z, a4.w};
            float b[4] = {b4.x, b4.y, b4.z, b4.w};
#pragma unroll
            for (int i = 0; i < 4; i++)
#pragma unroll
                for (int j = 0; j < 4; j++)
                    acc[i][j] = fmaf(a[i], b[j], acc[i][j]);
        }
        __syncthreads();
    }

#pragma unroll
    for (int i = 0; i < 4; i++) {
        const int m = m0 + ty * 4 + i;
        float4 o4 = make_float4(acc[i][0], acc[i][1], acc[i][2], acc[i][3]);
        *reinterpret_cast<float4*>(&outp[(size_t)m * DM + n0 + tx * 4]) = o4;
    }
}

// ---------------------------------------------------------------------------
// Launch. Inputs (metadata order): x, mask, Wq, Wk, Wv, Wo. Output fp32.
// ---------------------------------------------------------------------------
extern "C" void kernel_launch(void* const* d_in, const int* in_sizes, int n_in,
                              void* d_out, int out_size)
{
    const float* x    = (const float*)d_in[0];
    const void*  mask = d_in[1];
    const float* Wq   = (const float*)d_in[2];
    const float* Wk   = (const float*)d_in[3];
    const float* Wv   = (const float*)d_in[4];
    const float* Wo   = (const float*)d_in[5];
    float* outp = (float*)d_out;

    (void)in_sizes; (void)n_in; (void)out_size;

    // 0) Mask dtype detection + canonicalization to 1-byte 0/1
    mask_detect<<<1, 1024>>>((const unsigned*)mask);
    mask_convert<<<(BB * SEQ * SEQ / 4) / 256, 256>>>(mask);

    // 1) Q, K, V projections
    qkv_kernel<<<dim3(BB * SEQ / 64, NH, 3), 256>>>(x, Wq, Wk, Wv);

    // 2) Flash attention per (b, h, row-tile)
    attn_kernel<<<dim3(SEQ / 64, NH, BB), 256>>>();

    // 3) Output projection (sums heads)
    proj_kernel<<<dim3(BB * SEQ / 64, DM / 64), 256>>>(Wo, outp);
}

// round 5
// speedup vs baseline: 1.4336x; 1.4336x over previous
#include <cuda_runtime.h>
#include <cstdint>

#define BB 8
#define SEQ 1024
#define DM 512
#define NH 8
#define DK 64

// Scratch (allocation-free rule: __device__ globals).
__device__ float g_q[BB * NH * SEQ * DK];
__device__ float g_k[BB * NH * SEQ * DK];
__device__ float g_v[BB * NH * SEQ * DK];
__device__ float g_hd[BB * SEQ * DM];
__device__ uint8_t g_mask8[(size_t)BB * SEQ * SEQ];
__device__ unsigned g_flags[2];

// ===========================================================================
// tf32 helpers (baseline PTX, supported on plain sm_103 target)
// ===========================================================================
__device__ __forceinline__ uint32_t f2tf32(float f) {
    uint32_t u;
    asm("cvt.rna.tf32.f32 %0, %1;" : "=r"(u) : "f"(f));
    return u;
}

__device__ __forceinline__ void mma_tf32(float* c, const uint32_t* a,
                                         const uint32_t* b) {
    asm volatile(
        "mma.sync.aligned.m16n8k8.row.col.f32.tf32.tf32.f32 "
        "{%0,%1,%2,%3}, {%4,%5,%6,%7}, {%8,%9}, {%0,%1,%2,%3};"
        : "+f"(c[0]), "+f"(c[1]), "+f"(c[2]), "+f"(c[3])
        : "r"(a[0]), "r"(a[1]), "r"(a[2]), "r"(a[3]),
          "r"(b[0]), "r"(b[1]));
}

// ===========================================================================
// Mask dtype detection + canonicalization (unchanged from R3; proven).
// ===========================================================================
__global__ void mask_detect(const unsigned* __restrict__ m)
{
    __shared__ unsigned s0, s1;
    if (threadIdx.x == 0) { s0 = 0u; s1 = 0u; }
    __syncthreads();
    unsigned a0 = 0u, a1 = 0u;
    for (int i = threadIdx.x; i < 65536; i += blockDim.x) {
        const unsigned w = m[i];
        if (w > 1u) a0 = 1u;
        const unsigned b = w | (w >> 8) | (w >> 16) | (w >> 24);
        if (b & 0xFEu) a1 = 1u;
    }
    if (a0) atomicOr(&s0, 1u);
    if (a1) atomicOr(&s1, 1u);
    __syncthreads();
    if (threadIdx.x == 0) { g_flags[0] = s0; g_flags[1] = s1; }
}

__global__ __launch_bounds__(256) void mask_convert(const void* __restrict__ mraw)
{
    const size_t i = (size_t)blockIdx.x * 256 + threadIdx.x;
    const unsigned kind = (g_flags[0] == 0u) ? 0u : ((g_flags[1] == 0u) ? 1u : 2u);
    uchar4 o;
    if (kind == 0u) {
        const int4 v = reinterpret_cast<const int4*>(mraw)[i];
        o.x = (v.x != 0); o.y = (v.y != 0); o.z = (v.z != 0); o.w = (v.w != 0);
    } else if (kind == 1u) {
        o = reinterpret_cast<const uchar4*>(mraw)[i];
    } else {
        const float4 v = reinterpret_cast<const float4*>(mraw)[i];
        o.x = (v.x != 0.0f); o.y = (v.y != 0.0f);
        o.z = (v.z != 0.0f); o.w = (v.w != 0.0f);
    }
    reinterpret_cast<uchar4*>(g_mask8)[i] = o;
}

// ===========================================================================
// Warp-level mma.sync tf32 GEMM.
// mode 0 (qkv): A = x [8192][512]; B = W[blockIdx.y] [512][64]; z selects
//               Wq/Wk/Wv; out = g_q/g_k/g_v in [B,H,N,64] layout.
// mode 1 (proj): A = g_hd [8192][512]; B = Wo cols [512][512]; out = d_out.
// CTA tile M=128, N=64, K-chunk=32. 8 warps in 4(M) x 2(N); warp tile 32x32.
// SMEM stride 36 -> conflict-free fragment LDS (banks (4g+t)%32 distinct).
// ===========================================================================
__global__ __launch_bounds__(256) void gemm_mma(
    const float* __restrict__ x,
    const float* __restrict__ Wq, const float* __restrict__ Wk,
    const float* __restrict__ Wv, const float* __restrict__ Wo,
    float* __restrict__ outp, int mode)
{
    __shared__ uint32_t As[128][36];   // [m][k] tf32 bits
    __shared__ uint32_t Bs[64][36];    // [n][k] tf32 bits

    const int tid = threadIdx.x;
    const int wid = tid >> 5;
    const int lid = tid & 31;
    const int wm = wid & 3;          // warp M index (0..3)
    const int wn = wid >> 2;         // warp N index (0..1)
    const int g = lid >> 2;          // groupID
    const int t = lid & 3;           // threadID in group

    const float* __restrict__ A;
    const float* __restrict__ Bb;
    int ldb;
    if (mode == 0) {
        const int z = blockIdx.z;
        const float* W = (z == 0) ? Wq : ((z == 1) ? Wk : Wv);
        A = x;
        Bb = W + (size_t)blockIdx.y * DM * DK;
        ldb = DK;
    } else {
        A = g_hd;
        Bb = Wo + blockIdx.y * 64;
        ldb = DM;
    }
    const int m0 = blockIdx.x * 128;

    float acc[2][4][4];
#pragma unroll
    for (int i = 0; i < 2; i++)
#pragma unroll
        for (int j = 0; j < 4; j++)
#pragma unroll
            for (int e = 0; e < 4; e++) acc[i][j][e] = 0.0f;

    for (int k0 = 0; k0 < DM; k0 += 32) {
        // Load A tile: 128 rows x 32 k. 1024 float4 / 256 thr = 4 iters.
#pragma unroll
        for (int it = 0; it < 4; it++) {
            const int idx = it * 256 + tid;
            const int r = idx >> 3;
            const int q = idx & 7;
            const float4 v = *reinterpret_cast<const float4*>(
                &A[(size_t)(m0 + r) * DM + k0 + q * 4]);
            uint4 u = make_uint4(f2tf32(v.x), f2tf32(v.y),
                                 f2tf32(v.z), f2tf32(v.w));
            *reinterpret_cast<uint4*>(&As[r][q * 4]) = u;
        }
        // Load B tile transposed: Bs[n][k]. 512 float4 / 256 thr = 2 iters.
#pragma unroll
        for (int it = 0; it < 2; it++) {
            const int idx = it * 256 + tid;
            const int kk = idx >> 4;     // 0..31
            const int nq = idx & 15;     // n quad
            const float4 v = *reinterpret_cast<const float4*>(
                &Bb[(size_t)(k0 + kk) * ldb + nq * 4]);
            Bs[nq * 4 + 0][kk] = f2tf32(v.x);
            Bs[nq * 4 + 1][kk] = f2tf32(v.y);
            Bs[nq * 4 + 2][kk] = f2tf32(v.z);
            Bs[nq * 4 + 3][kk] = f2tf32(v.w);
        }
        __syncthreads();

#pragma unroll
        for (int kk = 0; kk < 4; kk++) {
            const int kb = kk * 8;
            uint32_t bf[4][2];
#pragma unroll
            for (int j = 0; j < 4; j++) {
                const int n = wn * 32 + j * 8 + g;
                bf[j][0] = Bs[n][kb + t];
                bf[j][1] = Bs[n][kb + t + 4];
            }
#pragma unroll
            for (int i = 0; i < 2; i++) {
                const int r0 = wm * 32 + i * 16 + g;
                uint32_t af[4];
                af[0] = As[r0][kb + t];
                af[1] = As[r0 + 8][kb + t];
                af[2] = As[r0][kb + t + 4];
                af[3] = As[r0 + 8][kb + t + 4];
#pragma unroll
                for (int j = 0; j < 4; j++)
                    mma_tf32(acc[i][j], af, bf[j]);
            }
        }
        __syncthreads();
    }

    // Epilogue: c0,c1 at (row g, cols 2t,2t+1); c2,c3 at (row g+8).
#pragma unroll
    for (int i = 0; i < 2; i++) {
#pragma unroll
        for (int rr = 0; rr < 2; rr++) {
            const int mg = m0 + wm * 32 + i * 16 + rr * 8 + g;
            float* dst;
            if (mode == 0) {
                const int z = blockIdx.z;
                float* outg = (z == 0) ? g_q : ((z == 1) ? g_k : g_v);
                const int b = mg >> 10;
                const int n = mg & 1023;
                dst = &outg[(((size_t)b * NH + blockIdx.y) * SEQ + n) * DK];
            } else {
                dst = &outp[(size_t)mg * DM + blockIdx.y * 64];
            }
#pragma unroll
            for (int j = 0; j < 4; j++) {
                const int col = wn * 32 + j * 8 + t * 2;
                float2 o2 = make_float2(acc[i][j][rr * 2 + 0],
                                        acc[i][j][rr * 2 + 1]);
                *reinterpret_cast<float2*>(&dst[col]) = o2;
            }
        }
    }
}

// ===========================================================================
// Kernel 2: flash attention (unchanged from R3 passing version).
// ===========================================================================
__global__ __launch_bounds__(256) void attn_kernel()
{
    __shared__ float Qs[64][64];
    __shared__ float Kst[64][64];
    __shared__ float Vs[64][64];

    const int r0 = blockIdx.x * 64;
    const int h  = blockIdx.y;
    const int b  = blockIdx.z;

    const int tid = threadIdx.x;
    const int tx = tid & 15;
    const int ty = tid >> 4;

    const size_t bh = (size_t)b * NH + h;
    const float* __restrict__ Qg = &g_q[bh * SEQ * DK];
    const float* __restrict__ Kg = &g_k[bh * SEQ * DK];
    const float* __restrict__ Vg = &g_v[bh * SEQ * DK];
    const uint8_t* __restrict__ Mg = &g_mask8[(size_t)b * SEQ * SEQ];

#pragma unroll
    for (int it = 0; it < 4; it++) {
        const int idx = tid + it * 256;
        const int qm = idx >> 4;
        const int qd = (idx & 15) * 4;
        *reinterpret_cast<float4*>(&Qs[qm][qd]) =
            *reinterpret_cast<const float4*>(&Qg[(size_t)(r0 + qm) * DK + qd]);
    }

    float o[4][4];
    float mi[4], li[4];
#pragma unroll
    for (int i = 0; i < 4; i++) {
        mi[i] = -1e30f;
        li[i] = 0.0f;
#pragma unroll
        for (int j = 0; j < 4; j++) o[i][j] = 0.0f;
    }

    const int km  = tid & 63;
    const int ks4 = tid >> 6;

    for (int m0 = 0; m0 < SEQ; m0 += 64) {
#pragma unroll
        for (int it = 0; it < 4; it++) {
            const int d0 = (ks4 + it * 4) * 4;
            float4 kv = *reinterpret_cast<const float4*>(
                &Kg[(size_t)(m0 + km) * DK + d0]);
            Kst[d0 + 0][km] = kv.x;
            Kst[d0 + 1][km] = kv.y;
            Kst[d0 + 2][km] = kv.z;
            Kst[d0 + 3][km] = kv.w;
        }
#pragma unroll
        for (int it = 0; it < 4; it++) {
            const int idx = tid + it * 256;
            const int vm = idx >> 4;
            const int vd = (idx & 15) * 4;
            *reinterpret_cast<float4*>(&Vs[vm][vd]) =
                *reinterpret_cast<const float4*>(&Vg[(size_t)(m0 + vm) * DK + vd]);
        }
        __syncthreads();

        float s[4][4];
#pragma unroll
        for (int i = 0; i < 4; i++)
#pragma unroll
            for (int j = 0; j < 4; j++) s[i][j] = 0.0f;

#pragma unroll
        for (int d = 0; d < 64; d += 4) {
            float qv[4][4];
#pragma unroll
            for (int i = 0; i < 4; i++) {
                float4 q4 = *reinterpret_cast<const float4*>(&Qs[ty * 4 + i][d]);
                qv[i][0] = q4.x; qv[i][1] = q4.y; qv[i][2] = q4.z; qv[i][3] = q4.w;
            }
#pragma unroll
            for (int c = 0; c < 4; c++) {
                float4 k4 = *reinterpret_cast<const float4*>(&Kst[d + c][tx * 4]);
                float kv[4] = {k4.x, k4.y, k4.z, k4.w};
#pragma unroll
                for (int i = 0; i < 4; i++)
#pragma unroll
                    for (int j = 0; j < 4; j++)
                        s[i][j] = fmaf(qv[i][c], kv[j], s[i][j]);
            }
        }
        __syncthreads();

#pragma unroll
        for (int i = 0; i < 4; i++) {
            const int gr = r0 + ty * 4 + i;
            uchar4 mk = *reinterpret_cast<const uchar4*>(
                &Mg[(size_t)gr * SEQ + m0 + tx * 4]);
            float sv[4];
            sv[0] = mk.x ? -1e9f : s[i][0] * 0.125f;
            sv[1] = mk.y ? -1e9f : s[i][1] * 0.125f;
            sv[2] = mk.z ? -1e9f : s[i][2] * 0.125f;
            sv[3] = mk.w ? -1e9f : s[i][3] * 0.125f;

            float rm = fmaxf(fmaxf(sv[0], sv[1]), fmaxf(sv[2], sv[3]));
#pragma unroll
            for (int w = 1; w < 16; w <<= 1)
                rm = fmaxf(rm, __shfl_xor_sync(0xffffffffu, rm, w));

            const float nm = fmaxf(mi[i], rm);
            const float corr = __expf(mi[i] - nm);
            float p[4];
            float rs = 0.0f;
#pragma unroll
            for (int j = 0; j < 4; j++) {
                p[j] = __expf(sv[j] - nm);
                rs += p[j];
            }
#pragma unroll
            for (int w = 1; w < 16; w <<= 1)
                rs += __shfl_xor_sync(0xffffffffu, rs, w);

            li[i] = li[i] * corr + rs;
            mi[i] = nm;
#pragma unroll
            for (int j = 0; j < 4; j++) o[i][j] *= corr;

            Kst[ty * 4 + i][tx * 4 + 0] = p[0];
            Kst[ty * 4 + i][tx * 4 + 1] = p[1];
            Kst[ty * 4 + i][tx * 4 + 2] = p[2];
            Kst[ty * 4 + i][tx * 4 + 3] = p[3];
        }
        __syncthreads();

#pragma unroll
        for (int m = 0; m < 64; m++) {
            float4 v4 = *reinterpret_cast<const float4*>(&Vs[m][tx * 4]);
            float vv[4] = {v4.x, v4.y, v4.z, v4.w};
            float pv[4];
#pragma unroll
            for (int i = 0; i < 4; i++) pv[i] = Kst[ty * 4 + i][m];
#pragma unroll
            for (int i = 0; i < 4; i++)
#pragma unroll
                for (int j = 0; j < 4; j++)
                    o[i][j] = fmaf(pv[i], vv[j], o[i][j]);
        }
        __syncthreads();
    }

#pragma unroll
    for (int i = 0; i < 4; i++) {
        const float inv = 1.0f / li[i];
        const int n = r0 + ty * 4 + i;
        float4 o4 = make_float4(o[i][0] * inv, o[i][1] * inv,
                                o[i][2] * inv, o[i][3] * inv);
        *reinterpret_cast<float4*>(
            &g_hd[((size_t)b * SEQ + n) * DM + h * DK + tx * 4]) = o4;
    }
}

// ===========================================================================
// Launch. Inputs (metadata order): x, mask, Wq, Wk, Wv, Wo. Output fp32.
// ===========================================================================
extern "C" void kernel_launch(void* const* d_in, const int* in_sizes, int n_in,
                              void* d_out, int out_size)
{
    const float* x    = (const float*)d_in[0];
    const void*  mask = d_in[1];
    const float* Wq   = (const float*)d_in[2];
    const float* Wk   = (const float*)d_in[3];
    const float* Wv   = (const float*)d_in[4];
    const float* Wo   = (const float*)d_in[5];
    float* outp = (float*)d_out;

    (void)in_sizes; (void)n_in; (void)out_size;

    // 0) Mask dtype detection + canonicalization to 1-byte 0/1
    mask_detect<<<1, 1024>>>((const unsigned*)mask);
    mask_convert<<<(BB * SEQ * SEQ / 4) / 256, 256>>>(mask);

    // 1) Q, K, V projections (mma.sync tf32)
    gemm_mma<<<dim3(BB * SEQ / 128, NH, 3), 256>>>(
        x, Wq, Wk, Wv, Wo, outp, 0);

    // 2) Flash attention per (b, h, row-tile)
    attn_kernel<<<dim3(SEQ / 64, NH, BB), 256>>>();

    // 3) Output projection (mma.sync tf32, head-sum folded into K)
    gemm_mma<<<dim3(BB * SEQ / 128, DM / 64, 1), 256>>>(
        x, Wq, Wk, Wv, Wo, outp, 1);
}

// round 6
// speedup vs baseline: 2.3333x; 1.6276x over previous
#include <cuda_runtime.h>
#include <cstdint>

#define BB 8
#define SEQ 1024
#define DM 512
#define NH 8
#define DK 64

// Scratch (allocation-free rule: __device__ globals).
__device__ float g_q[BB * NH * SEQ * DK];
__device__ float g_k[BB * NH * SEQ * DK];
__device__ float g_v[BB * NH * SEQ * DK];
__device__ float g_hd[BB * SEQ * DM];
__device__ uint8_t g_mask8[(size_t)BB * SEQ * SEQ];
__device__ unsigned g_flags[2];

// ===========================================================================
// tf32 helpers (baseline PTX, supported on plain sm_103 target)
// ===========================================================================
__device__ __forceinline__ uint32_t f2tf32(float f) {
    uint32_t u;
    asm("cvt.rna.tf32.f32 %0, %1;" : "=r"(u) : "f"(f));
    return u;
}

__device__ __forceinline__ void mma_tf32(float* c, const uint32_t* a,
                                         const uint32_t* b) {
    asm volatile(
        "mma.sync.aligned.m16n8k8.row.col.f32.tf32.tf32.f32 "
        "{%0,%1,%2,%3}, {%4,%5,%6,%7}, {%8,%9}, {%0,%1,%2,%3};"
        : "+f"(c[0]), "+f"(c[1]), "+f"(c[2]), "+f"(c[3])
        : "r"(a[0]), "r"(a[1]), "r"(a[2]), "r"(a[3]),
          "r"(b[0]), "r"(b[1]));
}

// ===========================================================================
// Mask dtype detection + canonicalization (proven).
// ===========================================================================
__global__ void mask_detect(const unsigned* __restrict__ m)
{
    __shared__ unsigned s0, s1;
    if (threadIdx.x == 0) { s0 = 0u; s1 = 0u; }
    __syncthreads();
    unsigned a0 = 0u, a1 = 0u;
    for (int i = threadIdx.x; i < 65536; i += blockDim.x) {
        const unsigned w = m[i];
        if (w > 1u) a0 = 1u;
        const unsigned b = w | (w >> 8) | (w >> 16) | (w >> 24);
        if (b & 0xFEu) a1 = 1u;
    }
    if (a0) atomicOr(&s0, 1u);
    if (a1) atomicOr(&s1, 1u);
    __syncthreads();
    if (threadIdx.x == 0) { g_flags[0] = s0; g_flags[1] = s1; }
}

__global__ __launch_bounds__(256) void mask_convert(const void* __restrict__ mraw)
{
    const size_t i = (size_t)blockIdx.x * 256 + threadIdx.x;
    const unsigned kind = (g_flags[0] == 0u) ? 0u : ((g_flags[1] == 0u) ? 1u : 2u);
    uchar4 o;
    if (kind == 0u) {
        const int4 v = reinterpret_cast<const int4*>(mraw)[i];
        o.x = (v.x != 0); o.y = (v.y != 0); o.z = (v.z != 0); o.w = (v.w != 0);
    } else if (kind == 1u) {
        o = reinterpret_cast<const uchar4*>(mraw)[i];
    } else {
        const float4 v = reinterpret_cast<const float4*>(mraw)[i];
        o.x = (v.x != 0.0f); o.y = (v.y != 0.0f);
        o.z = (v.z != 0.0f); o.w = (v.w != 0.0f);
    }
    reinterpret_cast<uchar4*>(g_mask8)[i] = o;
}

// ===========================================================================
// Warp-level mma.sync tf32 GEMM for projections (proven in R5).
// ===========================================================================
__global__ __launch_bounds__(256) void gemm_mma(
    const float* __restrict__ x,
    const float* __restrict__ Wq, const float* __restrict__ Wk,
    const float* __restrict__ Wv, const float* __restrict__ Wo,
    float* __restrict__ outp, int mode)
{
    __shared__ uint32_t As[128][36];
    __shared__ uint32_t Bs[64][36];

    const int tid = threadIdx.x;
    const int wid = tid >> 5;
    const int lid = tid & 31;
    const int wm = wid & 3;
    const int wn = wid >> 2;
    const int g = lid >> 2;
    const int t = lid & 3;

    const float* __restrict__ A;
    const float* __restrict__ Bb;
    int ldb;
    if (mode == 0) {
        const int z = blockIdx.z;
        const float* W = (z == 0) ? Wq : ((z == 1) ? Wk : Wv);
        A = x;
        Bb = W + (size_t)blockIdx.y * DM * DK;
        ldb = DK;
    } else {
        A = g_hd;
        Bb = Wo + blockIdx.y * 64;
        ldb = DM;
    }
    const int m0 = blockIdx.x * 128;

    float acc[2][4][4];
#pragma unroll
    for (int i = 0; i < 2; i++)
#pragma unroll
        for (int j = 0; j < 4; j++)
#pragma unroll
            for (int e = 0; e < 4; e++) acc[i][j][e] = 0.0f;

    for (int k0 = 0; k0 < DM; k0 += 32) {
#pragma unroll
        for (int it = 0; it < 4; it++) {
            const int idx = it * 256 + tid;
            const int r = idx >> 3;
            const int q = idx & 7;
            const float4 v = *reinterpret_cast<const float4*>(
                &A[(size_t)(m0 + r) * DM + k0 + q * 4]);
            uint4 u = make_uint4(f2tf32(v.x), f2tf32(v.y),
                                 f2tf32(v.z), f2tf32(v.w));
            *reinterpret_cast<uint4*>(&As[r][q * 4]) = u;
        }
#pragma unroll
        for (int it = 0; it < 2; it++) {
            const int idx = it * 256 + tid;
            const int kk = idx >> 4;
            const int nq = idx & 15;
            const float4 v = *reinterpret_cast<const float4*>(
                &Bb[(size_t)(k0 + kk) * ldb + nq * 4]);
            Bs[nq * 4 + 0][kk] = f2tf32(v.x);
            Bs[nq * 4 + 1][kk] = f2tf32(v.y);
            Bs[nq * 4 + 2][kk] = f2tf32(v.z);
            Bs[nq * 4 + 3][kk] = f2tf32(v.w);
        }
        __syncthreads();

#pragma unroll
        for (int kk = 0; kk < 4; kk++) {
            const int kb = kk * 8;
            uint32_t bf[4][2];
#pragma unroll
            for (int j = 0; j < 4; j++) {
                const int n = wn * 32 + j * 8 + g;
                bf[j][0] = Bs[n][kb + t];
                bf[j][1] = Bs[n][kb + t + 4];
            }
#pragma unroll
            for (int i = 0; i < 2; i++) {
                const int r0 = wm * 32 + i * 16 + g;
                uint32_t af[4];
                af[0] = As[r0][kb + t];
                af[1] = As[r0 + 8][kb + t];
                af[2] = As[r0][kb + t + 4];
                af[3] = As[r0 + 8][kb + t + 4];
#pragma unroll
                for (int j = 0; j < 4; j++)
                    mma_tf32(acc[i][j], af, bf[j]);
            }
        }
        __syncthreads();
    }

#pragma unroll
    for (int i = 0; i < 2; i++) {
#pragma unroll
        for (int rr = 0; rr < 2; rr++) {
            const int mg = m0 + wm * 32 + i * 16 + rr * 8 + g;
            float* dst;
            if (mode == 0) {
                const int z = blockIdx.z;
                float* outg = (z == 0) ? g_q : ((z == 1) ? g_k : g_v);
                const int b = mg >> 10;
                const int n = mg & 1023;
                dst = &outg[(((size_t)b * NH + blockIdx.y) * SEQ + n) * DK];
            } else {
                dst = &outp[(size_t)mg * DM + blockIdx.y * 64];
            }
#pragma unroll
            for (int j = 0; j < 4; j++) {
                const int col = wn * 32 + j * 8 + t * 2;
                float2 o2 = make_float2(acc[i][j][rr * 2 + 0],
                                        acc[i][j][rr * 2 + 1]);
                *reinterpret_cast<float2*>(&dst[col]) = o2;
            }
        }
    }
}

// ===========================================================================
// Flash attention on mma.sync tf32.
// CTA = 128 q-rows for one (b,h). 8 warps; warp w owns rows w*16..w*16+15
// (one m16 atom). Key loop in 64-wide tiles.
//   S = Q K^T   : A = Q frags (registers, loop-invariant), B = Ks[key][d]
//   softmax     : fp32 on accumulators, row reduce = shfl over 4 t-lanes
//   O += P V    : A = P (per-warp smem rows, tf32), B = Vt[d][key]
// Smem stride 68 => conflict-free fragment LDS. Dynamic smem 69632 B.
// ===========================================================================
#define PS_OFF 0                      // [128][68] u32 : Q staging, then P
#define KS_OFF (128 * 68)             // [64][68]  u32 : K tile [key][d]
#define VT_OFF (KS_OFF + 64 * 68)     // [64][68]  u32 : V tile [d][key]
#define ATT_SMEM ((VT_OFF + 64 * 68) * 4)

__global__ __launch_bounds__(256) void attn_kernel()
{
    extern __shared__ uint32_t dsm[];
    uint32_t* __restrict__ Ps = dsm + PS_OFF;
    uint32_t* __restrict__ Ks = dsm + KS_OFF;
    uint32_t* __restrict__ Vt = dsm + VT_OFF;

    const int r0 = blockIdx.x * 128;
    const int h  = blockIdx.y;
    const int b  = blockIdx.z;

    const int tid = threadIdx.x;
    const int w   = tid >> 5;
    const int lid = tid & 31;
    const int g   = lid >> 2;
    const int t   = lid & 3;
    const int wr  = w * 16;            // warp row base (local)

    const size_t bh = (size_t)b * NH + h;
    const float* __restrict__ Qg = &g_q[bh * SEQ * DK];
    const float* __restrict__ Kg = &g_k[bh * SEQ * DK];
    const float* __restrict__ Vg = &g_v[bh * SEQ * DK];
    const uint8_t* __restrict__ Mg = &g_mask8[(size_t)b * SEQ * SEQ];

    // --- Stage Q tile through Ps (coalesced), then load register fragments.
#pragma unroll
    for (int it = 0; it < 8; it++) {
        const int idx = it * 256 + tid;
        const int r = idx >> 4;
        const int q4 = idx & 15;
        const float4 v = *reinterpret_cast<const float4*>(
            &Qg[(size_t)(r0 + r) * DK + q4 * 4]);
        uint4 u = make_uint4(f2tf32(v.x), f2tf32(v.y), f2tf32(v.z), f2tf32(v.w));
        *reinterpret_cast<uint4*>(&Ps[r * 68 + q4 * 4]) = u;
    }
    __syncthreads();

    uint32_t aq[8][4];
    {
        const int rlo = (wr + g) * 68;
        const int rhi = rlo + 8 * 68;
#pragma unroll
        for (int ks = 0; ks < 8; ks++) {
            aq[ks][0] = Ps[rlo + ks * 8 + t];
            aq[ks][1] = Ps[rhi + ks * 8 + t];
            aq[ks][2] = Ps[rlo + ks * 8 + t + 4];
            aq[ks][3] = Ps[rhi + ks * 8 + t + 4];
        }
    }
    __syncthreads();

    // Online softmax state: rows g (lo) and g+8 (hi) of warp strip.
    float mi0 = -1e30f, mi1 = -1e30f, li0 = 0.0f, li1 = 0.0f;
    float oc[8][4];
#pragma unroll
    for (int j = 0; j < 8; j++)
#pragma unroll
        for (int e = 0; e < 4; e++) oc[j][e] = 0.0f;

    const int gr_lo = r0 + wr + g;
    const int gr_hi = gr_lo + 8;

    for (int m0 = 0; m0 < SEQ; m0 += 64) {
        // K tile: natural [key][d] layout (coalesced).
#pragma unroll
        for (int it = 0; it < 4; it++) {
            const int idx = it * 256 + tid;
            const int r = idx >> 4;
            const int q4 = idx & 15;
            const float4 v = *reinterpret_cast<const float4*>(
                &Kg[(size_t)(m0 + r) * DK + q4 * 4]);
            uint4 u = make_uint4(f2tf32(v.x), f2tf32(v.y),
                                 f2tf32(v.z), f2tf32(v.w));
            *reinterpret_cast<uint4*>(&Ks[r * 68 + q4 * 4]) = u;
        }
        // V tile transposed: Vt[d][key].
#pragma unroll
        for (int it = 0; it < 4; it++) {
            const int idx = it * 256 + tid;
            const int key = idx & 63;
            const int dq = idx >> 6;
            const float4 v = *reinterpret_cast<const float4*>(
                &Vg[(size_t)(m0 + key) * DK + dq * 4]);
            Vt[(dq * 4 + 0) * 68 + key] = f2tf32(v.x);
            Vt[(dq * 4 + 1) * 68 + key] = f2tf32(v.y);
            Vt[(dq * 4 + 2) * 68 + key] = f2tf32(v.z);
            Vt[(dq * 4 + 3) * 68 + key] = f2tf32(v.w);
        }
        __syncthreads();

        // ---- S = Q K^T  (8 n-atoms of 8 keys, 8 k-steps over d)
        float sacc[8][4];
#pragma unroll
        for (int j = 0; j < 8; j++)
#pragma unroll
            for (int e = 0; e < 4; e++) sacc[j][e] = 0.0f;

#pragma unroll
        for (int ks = 0; ks < 8; ks++) {
            const int kb = ks * 8;
#pragma unroll
            for (int j = 0; j < 8; j++) {
                uint32_t bf[2];
                bf[0] = Ks[(j * 8 + g) * 68 + kb + t];
                bf[1] = Ks[(j * 8 + g) * 68 + kb + t + 4];
                mma_tf32(sacc[j], aq[ks], bf);
            }
        }

        // ---- mask + scale (fp32)
#pragma unroll
        for (int j = 0; j < 8; j++) {
            const int col = m0 + j * 8 + 2 * t;
            const uchar2 mlo = *reinterpret_cast<const uchar2*>(
                &Mg[(size_t)gr_lo * SEQ + col]);
            const uchar2 mhi = *reinterpret_cast<const uchar2*>(
                &Mg[(size_t)gr_hi * SEQ + col]);
            sacc[j][0] = mlo.x ? -1e9f : sacc[j][0] * 0.125f;
            sacc[j][1] = mlo.y ? -1e9f : sacc[j][1] * 0.125f;
            sacc[j][2] = mhi.x ? -1e9f : sacc[j][2] * 0.125f;
            sacc[j][3] = mhi.y ? -1e9f : sacc[j][3] * 0.125f;
        }

        // ---- row max (reduce over 8 atoms, then 4 t-lanes)
        float mx0 = -1e30f, mx1 = -1e30f;
#pragma unroll
        for (int j = 0; j < 8; j++) {
            mx0 = fmaxf(mx0, fmaxf(sacc[j][0], sacc[j][1]));
            mx1 = fmaxf(mx1, fmaxf(sacc[j][2], sacc[j][3]));
        }
        mx0 = fmaxf(mx0, __shfl_xor_sync(0xffffffffu, mx0, 1));
        mx0 = fmaxf(mx0, __shfl_xor_sync(0xffffffffu, mx0, 2));
        mx1 = fmaxf(mx1, __shfl_xor_sync(0xffffffffu, mx1, 1));
        mx1 = fmaxf(mx1, __shfl_xor_sync(0xffffffffu, mx1, 2));

        const float nm0 = fmaxf(mi0, mx0);
        const float nm1 = fmaxf(mi1, mx1);
        const float corr0 = __expf(mi0 - nm0);
        const float corr1 = __expf(mi1 - nm1);
        mi0 = nm0; mi1 = nm1;

        // ---- P = exp(S - m), write tf32 to per-warp Ps rows, row sums
        float rs0 = 0.0f, rs1 = 0.0f;
        const int prlo = (wr + g) * 68;
        const int prhi = prlo + 8 * 68;
#pragma unroll
        for (int j = 0; j < 8; j++) {
            const float p0 = __expf(sacc[j][0] - nm0);
            const float p1 = __expf(sacc[j][1] - nm0);
            const float p2 = __expf(sacc[j][2] - nm1);
            const float p3 = __expf(sacc[j][3] - nm1);
            rs0 += p0 + p1;
            rs1 += p2 + p3;
            const int c = j * 8 + 2 * t;
            Ps[prlo + c]     = f2tf32(p0);
            Ps[prlo + c + 1] = f2tf32(p1);
            Ps[prhi + c]     = f2tf32(p2);
            Ps[prhi + c + 1] = f2tf32(p3);
        }
        rs0 += __shfl_xor_sync(0xffffffffu, rs0, 1);
        rs0 += __shfl_xor_sync(0xffffffffu, rs0, 2);
        rs1 += __shfl_xor_sync(0xffffffffu, rs1, 1);
        rs1 += __shfl_xor_sync(0xffffffffu, rs1, 2);
        li0 = li0 * corr0 + rs0;
        li1 = li1 * corr1 + rs1;

        // rescale O accumulators
#pragma unroll
        for (int j = 0; j < 8; j++) {
            oc[j][0] *= corr0; oc[j][1] *= corr0;
            oc[j][2] *= corr1; oc[j][3] *= corr1;
        }
        __syncwarp();

        // ---- O += P V  (k = keys, 8 steps; n = d, 8 atoms)
#pragma unroll
        for (int ks = 0; ks < 8; ks++) {
            const int kb = ks * 8;
            uint32_t ap[4];
            ap[0] = Ps[prlo + kb + t];
            ap[1] = Ps[prhi + kb + t];
            ap[2] = Ps[prlo + kb + t + 4];
            ap[3] = Ps[prhi + kb + t + 4];
#pragma unroll
            for (int j = 0; j < 8; j++) {
                uint32_t bf[2];
                bf[0] = Vt[(j * 8 + g) * 68 + kb + t];
                bf[1] = Vt[(j * 8 + g) * 68 + kb + t + 4];
                mma_tf32(oc[j], ap, bf);
            }
        }
        __syncthreads();   // Ks/Vt reused next tile
    }

    // ---- normalize + write heads [B, N, H*64]
    const float inv0 = 1.0f / li0;
    const float inv1 = 1.0f / li1;
    float* dlo = &g_hd[((size_t)b * SEQ + gr_lo) * DM + h * DK];
    float* dhi = &g_hd[((size_t)b * SEQ + gr_hi) * DM + h * DK];
#pragma unroll
    for (int j = 0; j < 8; j++) {
        const int c = j * 8 + 2 * t;
        *reinterpret_cast<float2*>(&dlo[c]) =
            make_float2(oc[j][0] * inv0, oc[j][1] * inv0);
        *reinterpret_cast<float2*>(&dhi[c]) =
            make_float2(oc[j][2] * inv1, oc[j][3] * inv1);
    }
}

// ===========================================================================
// Launch. Inputs (metadata order): x, mask, Wq, Wk, Wv, Wo. Output fp32.
// ===========================================================================
extern "C" void kernel_launch(void* const* d_in, const int* in_sizes, int n_in,
                              void* d_out, int out_size)
{
    const float* x    = (const float*)d_in[0];
    const void*  mask = d_in[1];
    const float* Wq   = (const float*)d_in[2];
    const float* Wk   = (const float*)d_in[3];
    const float* Wv   = (const float*)d_in[4];
    const float* Wo   = (const float*)d_in[5];
    float* outp = (float*)d_out;

    (void)in_sizes; (void)n_in; (void)out_size;

    cudaFuncSetAttribute(attn_kernel,
                         cudaFuncAttributeMaxDynamicSharedMemorySize, ATT_SMEM);

    // 0) Mask dtype detection + canonicalization to 1-byte 0/1
    mask_detect<<<1, 1024>>>((const unsigned*)mask);
    mask_convert<<<(BB * SEQ * SEQ / 4) / 256, 256>>>(mask);

    // 1) Q, K, V projections (mma.sync tf32)
    gemm_mma<<<dim3(BB * SEQ / 128, NH, 3), 256>>>(
        x, Wq, Wk, Wv, Wo, outp, 0);

    // 2) Flash attention (mma.sync tf32)
    attn_kernel<<<dim3(SEQ / 128, NH, BB), 256, ATT_SMEM>>>();

    // 3) Output projection (mma.sync tf32, head-sum folded into K)
    gemm_mma<<<dim3(BB * SEQ / 128, DM / 64, 1), 256>>>(
        x, Wq, Wk, Wv, Wo, outp, 1);
}

// round 7
// speedup vs baseline: 2.4357x; 1.0439x over previous
#include <cuda_runtime.h>
#include <cstdint>

#define BB 8
#define SEQ 1024
#define DM 512
#define NH 8
#define DK 64

// Scratch (allocation-free rule: __device__ globals).
__device__ float g_q[BB * NH * SEQ * DK];
__device__ float g_k[BB * NH * SEQ * DK];
__device__ float g_v[BB * NH * SEQ * DK];
__device__ float g_hd[BB * SEQ * DM];
__device__ uint8_t g_mask8[(size_t)BB * SEQ * SEQ];
__device__ unsigned g_flags[2];

// ===========================================================================
// tf32 helpers (baseline PTX, supported on plain sm_103 target)
// ===========================================================================
__device__ __forceinline__ uint32_t f2tf32(float f) {
    uint32_t u;
    asm("cvt.rna.tf32.f32 %0, %1;" : "=r"(u) : "f"(f));
    return u;
}

__device__ __forceinline__ void mma_tf32(float* c, const uint32_t* a,
                                         const uint32_t* b) {
    asm volatile(
        "mma.sync.aligned.m16n8k8.row.col.f32.tf32.tf32.f32 "
        "{%0,%1,%2,%3}, {%4,%5,%6,%7}, {%8,%9}, {%0,%1,%2,%3};"
        : "+f"(c[0]), "+f"(c[1]), "+f"(c[2]), "+f"(c[3])
        : "r"(a[0]), "r"(a[1]), "r"(a[2]), "r"(a[3]),
          "r"(b[0]), "r"(b[1]));
}

// ===========================================================================
// Mask dtype detection + canonicalization (proven).
// ===========================================================================
__global__ void mask_detect(const unsigned* __restrict__ m)
{
    __shared__ unsigned s0, s1;
    if (threadIdx.x == 0) { s0 = 0u; s1 = 0u; }
    __syncthreads();
    unsigned a0 = 0u, a1 = 0u;
    for (int i = threadIdx.x; i < 65536; i += blockDim.x) {
        const unsigned w = m[i];
        if (w > 1u) a0 = 1u;
        const unsigned b = w | (w >> 8) | (w >> 16) | (w >> 24);
        if (b & 0xFEu) a1 = 1u;
    }
    if (a0) atomicOr(&s0, 1u);
    if (a1) atomicOr(&s1, 1u);
    __syncthreads();
    if (threadIdx.x == 0) { g_flags[0] = s0; g_flags[1] = s1; }
}

__global__ __launch_bounds__(256) void mask_convert(const void* __restrict__ mraw)
{
    const size_t i = (size_t)blockIdx.x * 256 + threadIdx.x;
    const unsigned kind = (g_flags[0] == 0u) ? 0u : ((g_flags[1] == 0u) ? 1u : 2u);
    uchar4 o;
    if (kind == 0u) {
        const int4 v = reinterpret_cast<const int4*>(mraw)[i];
        o.x = (v.x != 0); o.y = (v.y != 0); o.z = (v.z != 0); o.w = (v.w != 0);
    } else if (kind == 1u) {
        o = reinterpret_cast<const uchar4*>(mraw)[i];
    } else {
        const float4 v = reinterpret_cast<const float4*>(mraw)[i];
        o.x = (v.x != 0.0f); o.y = (v.y != 0.0f);
        o.z = (v.z != 0.0f); o.w = (v.w != 0.0f);
    }
    reinterpret_cast<uchar4*>(g_mask8)[i] = o;
}

// ===========================================================================
// Warp-level mma.sync tf32 GEMM for projections (proven in R5; unchanged).
// ===========================================================================
__global__ __launch_bounds__(256) void gemm_mma(
    const float* __restrict__ x,
    const float* __restrict__ Wq, const float* __restrict__ Wk,
    const float* __restrict__ Wv, const float* __restrict__ Wo,
    float* __restrict__ outp, int mode)
{
    __shared__ uint32_t As[128][36];
    __shared__ uint32_t Bs[64][36];

    const int tid = threadIdx.x;
    const int wid = tid >> 5;
    const int lid = tid & 31;
    const int wm = wid & 3;
    const int wn = wid >> 2;
    const int g = lid >> 2;
    const int t = lid & 3;

    const float* __restrict__ A;
    const float* __restrict__ Bb;
    int ldb;
    if (mode == 0) {
        const int z = blockIdx.z;
        const float* W = (z == 0) ? Wq : ((z == 1) ? Wk : Wv);
        A = x;
        Bb = W + (size_t)blockIdx.y * DM * DK;
        ldb = DK;
    } else {
        A = g_hd;
        Bb = Wo + blockIdx.y * 64;
        ldb = DM;
    }
    const int m0 = blockIdx.x * 128;

    float acc[2][4][4];
#pragma unroll
    for (int i = 0; i < 2; i++)
#pragma unroll
        for (int j = 0; j < 4; j++)
#pragma unroll
            for (int e = 0; e < 4; e++) acc[i][j][e] = 0.0f;

    for (int k0 = 0; k0 < DM; k0 += 32) {
#pragma unroll
        for (int it = 0; it < 4; it++) {
            const int idx = it * 256 + tid;
            const int r = idx >> 3;
            const int q = idx & 7;
            const float4 v = *reinterpret_cast<const float4*>(
                &A[(size_t)(m0 + r) * DM + k0 + q * 4]);
            uint4 u = make_uint4(f2tf32(v.x), f2tf32(v.y),
                                 f2tf32(v.z), f2tf32(v.w));
            *reinterpret_cast<uint4*>(&As[r][q * 4]) = u;
        }
#pragma unroll
        for (int it = 0; it < 2; it++) {
            const int idx = it * 256 + tid;
            const int kk = idx >> 4;
            const int nq = idx & 15;
            const float4 v = *reinterpret_cast<const float4*>(
                &Bb[(size_t)(k0 + kk) * ldb + nq * 4]);
            Bs[nq * 4 + 0][kk] = f2tf32(v.x);
            Bs[nq * 4 + 1][kk] = f2tf32(v.y);
            Bs[nq * 4 + 2][kk] = f2tf32(v.z);
            Bs[nq * 4 + 3][kk] = f2tf32(v.w);
        }
        __syncthreads();

#pragma unroll
        for (int kk = 0; kk < 4; kk++) {
            const int kb = kk * 8;
            uint32_t bf[4][2];
#pragma unroll
            for (int j = 0; j < 4; j++) {
                const int n = wn * 32 + j * 8 + g;
                bf[j][0] = Bs[n][kb + t];
                bf[j][1] = Bs[n][kb + t + 4];
            }
#pragma unroll
            for (int i = 0; i < 2; i++) {
                const int r0 = wm * 32 + i * 16 + g;
                uint32_t af[4];
                af[0] = As[r0][kb + t];
                af[1] = As[r0 + 8][kb + t];
                af[2] = As[r0][kb + t + 4];
                af[3] = As[r0 + 8][kb + t + 4];
#pragma unroll
                for (int j = 0; j < 4; j++)
                    mma_tf32(acc[i][j], af, bf[j]);
            }
        }
        __syncthreads();
    }

#pragma unroll
    for (int i = 0; i < 2; i++) {
#pragma unroll
        for (int rr = 0; rr < 2; rr++) {
            const int mg = m0 + wm * 32 + i * 16 + rr * 8 + g;
            float* dst;
            if (mode == 0) {
                const int z = blockIdx.z;
                float* outg = (z == 0) ? g_q : ((z == 1) ? g_k : g_v);
                const int b = mg >> 10;
                const int n = mg & 1023;
                dst = &outg[(((size_t)b * NH + blockIdx.y) * SEQ + n) * DK];
            } else {
                dst = &outp[(size_t)mg * DM + blockIdx.y * 64];
            }
#pragma unroll
            for (int j = 0; j < 4; j++) {
                const int col = wn * 32 + j * 8 + t * 2;
                float2 o2 = make_float2(acc[i][j][rr * 2 + 0],
                                        acc[i][j][rr * 2 + 1]);
                *reinterpret_cast<float2*>(&dst[col]) = o2;
            }
        }
    }
}

// ===========================================================================
// Flash attention on mma.sync tf32 — 2 m-atoms per warp.
// CTA = 128 q-rows, 4 warps x 32 rows (two m16 atoms each), 128 threads.
// Each B-fragment LDS now feeds two MMAs (halves the dominant smem term).
// Smem stride 68 => conflict-free fragment LDS. Dynamic smem 69632 B.
// ===========================================================================
#define PS_OFF 0                      // [128][68] u32 : Q staging, then P
#define KS_OFF (128 * 68)             // [64][68]  u32 : K tile [key][d]
#define VT_OFF (KS_OFF + 64 * 68)     // [64][68]  u32 : V tile [d][key]
#define ATT_SMEM ((VT_OFF + 64 * 68) * 4)

__global__ __launch_bounds__(128) void attn_kernel()
{
    extern __shared__ uint32_t dsm[];
    uint32_t* __restrict__ Ps = dsm + PS_OFF;
    uint32_t* __restrict__ Ks = dsm + KS_OFF;
    uint32_t* __restrict__ Vt = dsm + VT_OFF;

    const int r0 = blockIdx.x * 128;
    const int h  = blockIdx.y;
    const int b  = blockIdx.z;

    const int tid = threadIdx.x;
    const int w   = tid >> 5;
    const int lid = tid & 31;
    const int g   = lid >> 2;
    const int t   = lid & 3;
    const int wr  = w * 32;            // warp row base (local, 32 rows)

    const size_t bh = (size_t)b * NH + h;
    const float* __restrict__ Qg = &g_q[bh * SEQ * DK];
    const float* __restrict__ Kg = &g_k[bh * SEQ * DK];
    const float* __restrict__ Vg = &g_v[bh * SEQ * DK];
    const uint8_t* __restrict__ Mg = &g_mask8[(size_t)b * SEQ * SEQ];

    // --- Stage Q tile through Ps (coalesced), then load register fragments.
#pragma unroll
    for (int it = 0; it < 16; it++) {
        const int idx = it * 128 + tid;
        const int r = idx >> 4;
        const int q4 = idx & 15;
        const float4 v = *reinterpret_cast<const float4*>(
            &Qg[(size_t)(r0 + r) * DK + q4 * 4]);
        uint4 u = make_uint4(f2tf32(v.x), f2tf32(v.y), f2tf32(v.z), f2tf32(v.w));
        *reinterpret_cast<uint4*>(&Ps[r * 68 + q4 * 4]) = u;
    }
    __syncthreads();

    // aq[ks][0..3] = atom0 (rows wr+g, wr+g+8); [4..7] = atom1 (+16, +24)
    uint32_t aq[8][8];
    {
        const int ra = (wr + g) * 68;
        const int rb = ra + 8 * 68;
        const int rc = ra + 16 * 68;
        const int rd = ra + 24 * 68;
#pragma unroll
        for (int ks = 0; ks < 8; ks++) {
            const int kb = ks * 8;
            aq[ks][0] = Ps[ra + kb + t];
            aq[ks][1] = Ps[rb + kb + t];
            aq[ks][2] = Ps[ra + kb + t + 4];
            aq[ks][3] = Ps[rb + kb + t + 4];
            aq[ks][4] = Ps[rc + kb + t];
            aq[ks][5] = Ps[rd + kb + t];
            aq[ks][6] = Ps[rc + kb + t + 4];
            aq[ks][7] = Ps[rd + kb + t + 4];
        }
    }
    __syncthreads();

    // Online softmax state per thread: 4 owned rows (2 atoms x {g, g+8}).
    float mi[2][2], li[2][2];
#pragma unroll
    for (int a = 0; a < 2; a++) {
        mi[a][0] = -1e30f; mi[a][1] = -1e30f;
        li[a][0] = 0.0f;   li[a][1] = 0.0f;
    }
    float oc[2][8][4];
#pragma unroll
    for (int a = 0; a < 2; a++)
#pragma unroll
        for (int j = 0; j < 8; j++)
#pragma unroll
            for (int e = 0; e < 4; e++) oc[a][j][e] = 0.0f;

    for (int m0 = 0; m0 < SEQ; m0 += 64) {
        // K tile: natural [key][d] layout (coalesced).
#pragma unroll
        for (int it = 0; it < 8; it++) {
            const int idx = it * 128 + tid;
            const int r = idx >> 4;
            const int q4 = idx & 15;
            const float4 v = *reinterpret_cast<const float4*>(
                &Kg[(size_t)(m0 + r) * DK + q4 * 4]);
            uint4 u = make_uint4(f2tf32(v.x), f2tf32(v.y),
                                 f2tf32(v.z), f2tf32(v.w));
            *reinterpret_cast<uint4*>(&Ks[r * 68 + q4 * 4]) = u;
        }
        // V tile transposed: Vt[d][key].
#pragma unroll
        for (int it = 0; it < 8; it++) {
            const int idx = it * 128 + tid;
            const int key = idx & 63;
            const int dq = idx >> 6;
            const float4 v = *reinterpret_cast<const float4*>(
                &Vg[(size_t)(m0 + key) * DK + dq * 4]);
            Vt[(dq * 4 + 0) * 68 + key] = f2tf32(v.x);
            Vt[(dq * 4 + 1) * 68 + key] = f2tf32(v.y);
            Vt[(dq * 4 + 2) * 68 + key] = f2tf32(v.z);
            Vt[(dq * 4 + 3) * 68 + key] = f2tf32(v.w);
        }
        __syncthreads();

        // ---- S = Q K^T : one bf load feeds both m-atoms.
        float sacc[2][8][4];
#pragma unroll
        for (int a = 0; a < 2; a++)
#pragma unroll
            for (int j = 0; j < 8; j++)
#pragma unroll
                for (int e = 0; e < 4; e++) sacc[a][j][e] = 0.0f;

#pragma unroll
        for (int ks = 0; ks < 8; ks++) {
            const int kb = ks * 8;
#pragma unroll
            for (int j = 0; j < 8; j++) {
                uint32_t bf[2];
                bf[0] = Ks[(j * 8 + g) * 68 + kb + t];
                bf[1] = Ks[(j * 8 + g) * 68 + kb + t + 4];
                mma_tf32(sacc[0][j], aq[ks], bf);
                mma_tf32(sacc[1][j], aq[ks] + 4, bf);
            }
        }

        // ---- mask + scale + online softmax per atom.
        const int prbase = (wr + g) * 68;
#pragma unroll
        for (int a = 0; a < 2; a++) {
            const int gr_lo = r0 + wr + g + a * 16;
            const int gr_hi = gr_lo + 8;
#pragma unroll
            for (int j = 0; j < 8; j++) {
                const int col = m0 + j * 8 + 2 * t;
                const uchar2 mlo = *reinterpret_cast<const uchar2*>(
                    &Mg[(size_t)gr_lo * SEQ + col]);
                const uchar2 mhi = *reinterpret_cast<const uchar2*>(
                    &Mg[(size_t)gr_hi * SEQ + col]);
                sacc[a][j][0] = mlo.x ? -1e9f : sacc[a][j][0] * 0.125f;
                sacc[a][j][1] = mlo.y ? -1e9f : sacc[a][j][1] * 0.125f;
                sacc[a][j][2] = mhi.x ? -1e9f : sacc[a][j][2] * 0.125f;
                sacc[a][j][3] = mhi.y ? -1e9f : sacc[a][j][3] * 0.125f;
            }

            float mx0 = -1e30f, mx1 = -1e30f;
#pragma unroll
            for (int j = 0; j < 8; j++) {
                mx0 = fmaxf(mx0, fmaxf(sacc[a][j][0], sacc[a][j][1]));
                mx1 = fmaxf(mx1, fmaxf(sacc[a][j][2], sacc[a][j][3]));
            }
            mx0 = fmaxf(mx0, __shfl_xor_sync(0xffffffffu, mx0, 1));
            mx0 = fmaxf(mx0, __shfl_xor_sync(0xffffffffu, mx0, 2));
            mx1 = fmaxf(mx1, __shfl_xor_sync(0xffffffffu, mx1, 1));
            mx1 = fmaxf(mx1, __shfl_xor_sync(0xffffffffu, mx1, 2));

            const float nm0 = fmaxf(mi[a][0], mx0);
            const float nm1 = fmaxf(mi[a][1], mx1);
            const float corr0 = __expf(mi[a][0] - nm0);
            const float corr1 = __expf(mi[a][1] - nm1);
            mi[a][0] = nm0; mi[a][1] = nm1;

            float rs0 = 0.0f, rs1 = 0.0f;
            const int prlo = prbase + a * 16 * 68;
            const int prhi = prlo + 8 * 68;
#pragma unroll
            for (int j = 0; j < 8; j++) {
                const float p0 = __expf(sacc[a][j][0] - nm0);
                const float p1 = __expf(sacc[a][j][1] - nm0);
                const float p2 = __expf(sacc[a][j][2] - nm1);
                const float p3 = __expf(sacc[a][j][3] - nm1);
                rs0 += p0 + p1;
                rs1 += p2 + p3;
                const int c = j * 8 + 2 * t;
                Ps[prlo + c]     = f2tf32(p0);
                Ps[prlo + c + 1] = f2tf32(p1);
                Ps[prhi + c]     = f2tf32(p2);
                Ps[prhi + c + 1] = f2tf32(p3);
            }
            rs0 += __shfl_xor_sync(0xffffffffu, rs0, 1);
            rs0 += __shfl_xor_sync(0xffffffffu, rs0, 2);
            rs1 += __shfl_xor_sync(0xffffffffu, rs1, 1);
            rs1 += __shfl_xor_sync(0xffffffffu, rs1, 2);
            li[a][0] = li[a][0] * corr0 + rs0;
            li[a][1] = li[a][1] * corr1 + rs1;

#pragma unroll
            for (int j = 0; j < 8; j++) {
                oc[a][j][0] *= corr0; oc[a][j][1] *= corr0;
                oc[a][j][2] *= corr1; oc[a][j][3] *= corr1;
            }
        }
        __syncwarp();

        // ---- O += P V : one bf load feeds both m-atoms.
#pragma unroll
        for (int ks = 0; ks < 8; ks++) {
            const int kb = ks * 8;
            uint32_t ap[8];
            const int prlo = prbase;
            ap[0] = Ps[prlo + kb + t];
            ap[1] = Ps[prlo + 8 * 68 + kb + t];
            ap[2] = Ps[prlo + kb + t + 4];
            ap[3] = Ps[prlo + 8 * 68 + kb + t + 4];
            ap[4] = Ps[prlo + 16 * 68 + kb + t];
            ap[5] = Ps[prlo + 24 * 68 + kb + t];
            ap[6] = Ps[prlo + 16 * 68 + kb + t + 4];
            ap[7] = Ps[prlo + 24 * 68 + kb + t + 4];
#pragma unroll
            for (int j = 0; j < 8; j++) {
                uint32_t bf[2];
                bf[0] = Vt[(j * 8 + g) * 68 + kb + t];
                bf[1] = Vt[(j * 8 + g) * 68 + kb + t + 4];
                mma_tf32(oc[0][j], ap, bf);
                mma_tf32(oc[1][j], ap + 4, bf);
            }
        }
        __syncthreads();   // Ks/Vt reused next tile
    }

    // ---- normalize + write heads [B, N, H*64]
#pragma unroll
    for (int a = 0; a < 2; a++) {
        const float inv0 = 1.0f / li[a][0];
        const float inv1 = 1.0f / li[a][1];
        const int gr_lo = r0 + wr + g + a * 16;
        float* dlo = &g_hd[((size_t)b * SEQ + gr_lo) * DM + h * DK];
        float* dhi = &g_hd[((size_t)b * SEQ + gr_lo + 8) * DM + h * DK];
#pragma unroll
        for (int j = 0; j < 8; j++) {
            const int c = j * 8 + 2 * t;
            *reinterpret_cast<float2*>(&dlo[c]) =
                make_float2(oc[a][j][0] * inv0, oc[a][j][1] * inv0);
            *reinterpret_cast<float2*>(&dhi[c]) =
                make_float2(oc[a][j][2] * inv1, oc[a][j][3] * inv1);
        }
    }
}

// ===========================================================================
// Launch. Inputs (metadata order): x, mask, Wq, Wk, Wv, Wo. Output fp32.
// ===========================================================================
extern "C" void kernel_launch(void* const* d_in, const int* in_sizes, int n_in,
                              void* d_out, int out_size)
{
    const float* x    = (const float*)d_in[0];
    const void*  mask = d_in[1];
    const float* Wq   = (const float*)d_in[2];
    const float* Wk   = (const float*)d_in[3];
    const float* Wv   = (const float*)d_in[4];
    const float* Wo   = (const float*)d_in[5];
    float* outp = (float*)d_out;

    (void)in_sizes; (void)n_in; (void)out_size;

    cudaFuncSetAttribute(attn_kernel,
                         cudaFuncAttributeMaxDynamicSharedMemorySize, ATT_SMEM);

    // 0) Mask dtype detection + canonicalization to 1-byte 0/1
    mask_detect<<<1, 1024>>>((const unsigned*)mask);
    mask_convert<<<(BB * SEQ * SEQ / 4) / 256, 256>>>(mask);

    // 1) Q, K, V projections (mma.sync tf32)
    gemm_mma<<<dim3(BB * SEQ / 128, NH, 3), 256>>>(
        x, Wq, Wk, Wv, Wo, outp, 0);

    // 2) Flash attention (mma.sync tf32, 2 m-atoms/warp)
    attn_kernel<<<dim3(SEQ / 128, NH, BB), 128, ATT_SMEM>>>();

    // 3) Output projection (mma.sync tf32, head-sum folded into K)
    gemm_mma<<<dim3(BB * SEQ / 128, DM / 64, 1), 256>>>(
        x, Wq, Wk, Wv, Wo, outp, 1);
}